// round 2
// baseline (speedup 1.0000x reference)
#include <cuda_runtime.h>

#define FULL 0xffffffffu

constexpr int NN   = 50000;
constexpr int NE   = 400000;
constexpr int F    = 32;
constexpr int H    = 4;
constexpr int ROWS = NN * H;        // 200000 (n,h) rows
constexpr int NG   = NE / H;        // 100000 message groups

// ---- scratch (device globals; no allocation allowed) ----
__device__ float    g_h[ROWS * F];      // current node features (N,H,F)
__device__ float    g_atom[ROWS * F];   // atom_in (N,H,F)
__device__ float    g_xs[ROWS * F];
__device__ float    g_xd[ROWS * F];
__device__ float    g_xm[ROWS * F];
__device__ float    g_ea[NE * F];       // attn edge embed (E,32)
__device__ float    g_em[NE * F];       // msg  edge embed (E,32)
__device__ float    g_exp[NE * H];      // alpha_raw, then exp_a (E,4)
__device__ unsigned g_nmaxu[NN];        // order-encoded float max
__device__ float    g_nsum[NN];
__device__ float    g_aggr[ROWS * F];   // aggr_flat; only rows < NN ever written

__device__ __forceinline__ unsigned fenc(float f) {
    unsigned u = __float_as_uint(f);
    return (u & 0x80000000u) ? ~u : (u | 0x80000000u);
}
__device__ __forceinline__ float fdec(unsigned u) {
    return __uint_as_float((u & 0x80000000u) ? (u & 0x7fffffffu) : ~u);
}

// ---- K0: atom_in = relu(x @ atom_w + atom_b), also h = atom_in ----
__global__ void k_atom(const float* __restrict__ x,
                       const float* __restrict__ w,
                       const float* __restrict__ b) {
    int lane = threadIdx.x & 31;
    int gw = (blockIdx.x * blockDim.x + threadIdx.x) >> 5;
    int nw = (gridDim.x * blockDim.x) >> 5;
    float4 b4 = ((const float4*)b)[lane];
    for (int n = gw; n < NN; n += nw) {
        float4 xv = ((const float4*)x)[n * 32 + lane];
        float4 acc = b4;
#pragma unroll
        for (int k = 0; k < 128; k++) {
            float xk = __shfl_sync(FULL, ((const float*)&xv)[k & 3], k >> 2);
            float4 w4 = ((const float4*)w)[k * 32 + lane];
            acc.x += xk * w4.x; acc.y += xk * w4.y;
            acc.z += xk * w4.z; acc.w += xk * w4.w;
        }
        acc.x = fmaxf(acc.x, 0.f); acc.y = fmaxf(acc.y, 0.f);
        acc.z = fmaxf(acc.z, 0.f); acc.w = fmaxf(acc.w, 0.f);
        ((float4*)g_atom)[n * 32 + lane] = acc;
        ((float4*)g_h)[n * 32 + lane]   = acc;
    }
}

// ---- K1: fused node linears: xs/xd/xm = h @ {asw,adw,mdw} + bias ----
__global__ void __launch_bounds__(256) k_nlin3(
        const float* __restrict__ ws, const float* __restrict__ bs,
        const float* __restrict__ wd, const float* __restrict__ bd,
        const float* __restrict__ wm, const float* __restrict__ bm) {
    int lane = threadIdx.x & 31;
    float wrs[32], wrd[32], wrm[32];
#pragma unroll
    for (int k = 0; k < 32; k++) {
        wrs[k] = ws[k * 32 + lane];
        wrd[k] = wd[k * 32 + lane];
        wrm[k] = wm[k * 32 + lane];
    }
    float bfs = bs[lane], bfd = bd[lane], bfm = bm[lane];
    int gw = (blockIdx.x * blockDim.x + threadIdx.x) >> 5;
    int nw = (gridDim.x * blockDim.x) >> 5;
    for (int r = gw; r < ROWS; r += nw) {
        float hv = g_h[r * 32 + lane];
        float as = bfs, ad = bfd, am = bfm;
#pragma unroll
        for (int k = 0; k < 32; k++) {
            float x = __shfl_sync(FULL, hv, k);
            as += x * wrs[k];
            ad += x * wrd[k];
            am += x * wrm[k];
        }
        g_xs[r * 32 + lane] = as;
        g_xd[r * 32 + lane] = ad;
        g_xm[r * 32 + lane] = am;
    }
}

// ---- K2: fused edge linears: ea/em = edge_attr @ {aew,mew} + bias ----
__global__ void __launch_bounds__(256) k_elin(
        const float* __restrict__ eattr,
        const float* __restrict__ wa, const float* __restrict__ ba,
        const float* __restrict__ wm, const float* __restrict__ bm) {
    int lane = threadIdx.x & 31;
    float wra[32], wrm[32];
#pragma unroll
    for (int k = 0; k < 32; k++) {
        wra[k] = wa[k * 32 + lane];
        wrm[k] = wm[k * 32 + lane];
    }
    float bfa = ba[lane], bfm = bm[lane];
    int gw = (blockIdx.x * blockDim.x + threadIdx.x) >> 5;
    int nw = (gridDim.x * blockDim.x) >> 5;
    for (int e = gw; e < NE; e += nw) {
        float ev = eattr[e * 32 + lane];
        float aa = bfa, am = bfm;
#pragma unroll
        for (int k = 0; k < 32; k++) {
            float x = __shfl_sync(FULL, ev, k);
            aa += x * wra[k];
            am += x * wrm[k];
        }
        g_ea[e * 32 + lane] = aa;
        g_em[e * 32 + lane] = am;
    }
}

// ---- K3: zero aggr/nsum, init nmax to encoded -inf ----
__global__ void k_init() {
    int i = blockIdx.x * blockDim.x + threadIdx.x;
    int stride = gridDim.x * blockDim.x;
    for (int j = i; j < ROWS * F / 4; j += stride)
        ((float4*)g_aggr)[j] = make_float4(0.f, 0.f, 0.f, 0.f);
    for (int j = i; j < NN; j += stride) {
        g_nsum[j]  = 0.f;
        g_nmaxu[j] = 0x007FFFFFu;   // fenc(-inf)
    }
}

// ---- K4: edge attention scores + segment max ----
// warp per edge; lane = h*8+q covers head h, feature chunk q*4..q*4+3
__global__ void k_attn(const int* __restrict__ ei,
                       const float* __restrict__ dw, const float* __restrict__ db) {
    int lane = threadIdx.x & 31;
    int q = lane & 7;
    float4 dw4 = ((const float4*)dw)[q];
    float dbv = db[0];
    int gw = (blockIdx.x * blockDim.x + threadIdx.x) >> 5;
    int nw = (gridDim.x * blockDim.x) >> 5;
    for (int e = gw; e < NE; e += nw) {
        int s = __ldg(ei + e);
        int d = __ldg(ei + NE + e);
        float4 a = ((const float4*)g_xs)[d * 32 + lane];
        float4 c = ((const float4*)g_xd)[s * 32 + lane];
        float4 ea = ((const float4*)g_ea)[e * 8 + q];
        float v = fmaxf(a.x + c.x + ea.x, 0.f) * dw4.x;
        v += fmaxf(a.y + c.y + ea.y, 0.f) * dw4.y;
        v += fmaxf(a.z + c.z + ea.z, 0.f) * dw4.z;
        v += fmaxf(a.w + c.w + ea.w, 0.f) * dw4.w;
        // reduce over the 8 lanes of this head
        v += __shfl_xor_sync(FULL, v, 4);
        v += __shfl_xor_sync(FULL, v, 2);
        v += __shfl_xor_sync(FULL, v, 1);
        v += dbv;                       // all lanes of group hold ar[h]
        // max across the 4 heads
        float m = fmaxf(v, __shfl_xor_sync(FULL, v, 8));
        m = fmaxf(m, __shfl_xor_sync(FULL, m, 16));
        float ar = __shfl_sync(FULL, v, (lane & 3) * 8);
        if (lane < 4) g_exp[e * 4 + lane] = ar;
        if (lane == 0) atomicMax(&g_nmaxu[d], fenc(m));
    }
}

// ---- K5: exp + segment sum ----
__global__ void k_exp(const int* __restrict__ ei) {
    int e = blockIdx.x * blockDim.x + threadIdx.x;
    if (e >= NE) return;
    int d = ei[NE + e];
    float nm = fdec(g_nmaxu[d]);
    float4 a = ((float4*)g_exp)[e];
    a.x = expf(a.x - nm); a.y = expf(a.y - nm);
    a.z = expf(a.z - nm); a.w = expf(a.w - nm);
    ((float4*)g_exp)[e] = a;
    atomicAdd(&g_nsum[d], a.x + a.y + a.z + a.w);
}

// ---- K6: messages + tiled scatter ----
// Reference scatters msg row m=(e,h) to segment dst[m mod E]. Row r=4g+j
// receives sum over c of alpha[e_c=c*NG+g, j] * (xm[dst[e_c], j, :] + em[e_c]).
// lane = j*8+q: head j, feature chunk q*4..q*4+3; one red.v4 per lane.
__global__ void k_msg(const int* __restrict__ ei) {
    int lane = threadIdx.x & 31;
    int q = lane & 7;
    int j = lane >> 3;
    int gw = (blockIdx.x * blockDim.x + threadIdx.x) >> 5;
    int nw = (gridDim.x * blockDim.x) >> 5;
    for (int g = gw; g < NG; g += nw) {
        float4 T = make_float4(0.f, 0.f, 0.f, 0.f);
#pragma unroll
        for (int c = 0; c < 4; c++) {
            int e = c * NG + g;
            int d = __ldg(ei + NE + e);
            float4 ex = ((const float4*)g_exp)[e];
            float inv = 1.f / (g_nsum[d] + 1e-8f);
            float exh = (j == 0) ? ex.x : (j == 1) ? ex.y : (j == 2) ? ex.z : ex.w;
            float sA = exh * inv;
            float4 xm = ((const float4*)g_xm)[d * 32 + lane];
            float4 em = ((const float4*)g_em)[e * 8 + q];
            T.x += sA * (xm.x + em.x);
            T.y += sA * (xm.y + em.y);
            T.z += sA * (xm.z + em.z);
            T.w += sA * (xm.w + em.w);
        }
        int tgt = __ldg(ei + NE + 4 * g + j);
        float* p = g_aggr + (size_t)tgt * 32 + q * 4;
        asm volatile("red.global.add.v4.f32 [%0], {%1,%2,%3,%4};"
                     :: "l"(p), "f"(T.x), "f"(T.y), "f"(T.z), "f"(T.w)
                     : "memory");
    }
}

// ---- K7: h = relu(aggr + h @ wnw + wnb + atom_in) ----
__global__ void k_comb(const float* __restrict__ w, const float* __restrict__ b) {
    int lane = threadIdx.x & 31;
    float wr[32];
#pragma unroll
    for (int k = 0; k < 32; k++) wr[k] = w[k * 32 + lane];
    float bf = b[lane];
    int gw = (blockIdx.x * blockDim.x + threadIdx.x) >> 5;
    int nw = (gridDim.x * blockDim.x) >> 5;
    for (int r = gw; r < ROWS; r += nw) {
        float hv = g_h[r * 32 + lane];
        float acc = bf;
#pragma unroll
        for (int k = 0; k < 32; k++)
            acc += __shfl_sync(FULL, hv, k) * wr[k];
        float v = g_aggr[r * 32 + lane] + acc + g_atom[r * 32 + lane];
        g_h[r * 32 + lane] = fmaxf(v, 0.f);
    }
}

// ---- K8: out[n,f] = mean over heads ----
__global__ void k_mean(float* __restrict__ out) {
    int i = blockIdx.x * blockDim.x + threadIdx.x;
    if (i >= NN * F) return;
    int n = i >> 5;
    int f = i & 31;
    const float* p = g_h + n * 128 + f;
    out[i] = 0.25f * (p[0] + p[32] + p[64] + p[96]);
}

extern "C" void kernel_launch(void* const* d_in, const int* in_sizes, int n_in,
                              void* d_out, int out_size) {
    const float* x      = (const float*)d_in[0];
    const float* eattr  = (const float*)d_in[1];
    const int*   ei     = (const int*)d_in[2];
    const float* atom_w = (const float*)d_in[3];
    const float* atom_b = (const float*)d_in[4];
    const float* asw  = (const float*)d_in[5];
    const float* asb  = (const float*)d_in[6];
    const float* adw  = (const float*)d_in[7];
    const float* adb  = (const float*)d_in[8];
    const float* aew  = (const float*)d_in[9];
    const float* aeb  = (const float*)d_in[10];
    const float* dotw = (const float*)d_in[11];
    const float* dotb = (const float*)d_in[12];
    const float* mdw  = (const float*)d_in[13];
    const float* mdb  = (const float*)d_in[14];
    const float* mew  = (const float*)d_in[15];
    const float* meb  = (const float*)d_in[16];
    const float* wnw  = (const float*)d_in[17];
    const float* wnb  = (const float*)d_in[18];
    float* out = (float*)d_out;

    k_atom<<<512, 256>>>(x, atom_w, atom_b);
    for (int l = 0; l < 2; l++) {
        int wo = l * 32 * 32, bo = l * 32;
        k_init<<<512, 256>>>();
        k_nlin3<<<1024, 256>>>(asw + wo, asb + bo, adw + wo, adb + bo,
                               mdw + wo, mdb + bo);
        k_elin<<<1024, 256>>>(eattr, aew + wo, aeb + bo, mew + wo, meb + bo);
        k_attn<<<1024, 256>>>(ei, dotw + l * 32, dotb + l);
        k_exp<<<(NE + 255) / 256, 256>>>(ei);
        k_msg<<<1024, 256>>>(ei);
        k_comb<<<1024, 256>>>(wnw + wo, wnb + bo);
    }
    k_mean<<<(NN * F + 255) / 256, 256>>>(out);
}

// round 3
// speedup vs baseline: 1.3135x; 1.3135x over previous
#include <cuda_runtime.h>
#include <cstdint>

#define FULL 0xffffffffu

constexpr int NN   = 50000;
constexpr int NE   = 400000;
constexpr int F    = 32;
constexpr int H    = 4;
constexpr int ROWS = NN * H;        // 200000 (n,h) rows
constexpr int NG   = NE / H;        // 100000 message groups

// ---- scratch (device globals; no allocation allowed) ----
__device__ float    g_h[ROWS * F];
__device__ float    g_atom[ROWS * F];
__device__ float    g_xs[ROWS * F];
__device__ float    g_xd[ROWS * F];
__device__ float    g_xm[ROWS * F];
__device__ float    g_ea[NE * F];
__device__ float    g_em[NE * F];
__device__ float    g_exp[NE * H];
__device__ unsigned g_nmaxu[NN];
__device__ float    g_nsum[NN];
__device__ float    g_aggr[ROWS * F];

__device__ __forceinline__ unsigned fenc(float f) {
    unsigned u = __float_as_uint(f);
    return (u & 0x80000000u) ? ~u : (u | 0x80000000u);
}
__device__ __forceinline__ float fdec(unsigned u) {
    return __uint_as_float((u & 0x80000000u) ? (u & 0x7fffffffu) : ~u);
}

__device__ __forceinline__ uint32_t f2tf(float v) {
    uint32_t r;
    asm("cvt.rna.tf32.f32 %0, %1;" : "=r"(r) : "f"(v));
    return r;
}

__device__ __forceinline__ void mma8(float d[4], const uint32_t a[4],
                                     uint32_t b0, uint32_t b1) {
    asm("mma.sync.aligned.m16n8k8.row.col.f32.tf32.tf32.f32 "
        "{%0,%1,%2,%3}, {%4,%5,%6,%7}, {%8,%9}, {%0,%1,%2,%3};"
        : "+f"(d[0]), "+f"(d[1]), "+f"(d[2]), "+f"(d[3])
        : "r"(a[0]), "r"(a[1]), "r"(a[2]), "r"(a[3]), "r"(b0), "r"(b1));
}

struct GArgs {
    const float* A;
    const float* B[3];
    const float* bias[3];
    float*       out[3];
    int          M;
};

// ---- generic K=32 GEMM: out[m] = A @ B[m] + bias[m]  (3xTF32 tensor core) ----
// MODE 0 = plain; MODE 2 = comb epilogue (+aggr +atom, relu, in-place on g_h)
template<int NM, int MODE>
__global__ void __launch_bounds__(256) k_gemm(GArgs ga) {
    constexpr int NT = NM * 4;           // 8-col n-tiles
    constexpr int PITCH = NT * 8 + 8;    // PITCH % 32 == 8 -> conflict-free
    __shared__ uint32_t sB[2][32 * PITCH];

    int tid = threadIdx.x;
    // stage B hi/lo (tf32 split)
    for (int m = 0; m < NM; m++) {
        for (int i = tid; i < 32 * 32; i += 256) {
            int k = i >> 5, n = i & 31;
            float v = ga.B[m][i];
            uint32_t hi = f2tf(v);
            float lo = v - __uint_as_float(hi);
            sB[0][k * PITCH + m * 32 + n] = hi;
            sB[1][k * PITCH + m * 32 + n] = f2tf(lo);
        }
    }
    __syncthreads();

    int lane = tid & 31;
    int gid = lane >> 2, tig = lane & 3;
    int gw = (blockIdx.x * 256 + tid) >> 5;
    int nw = (gridDim.x * 256) >> 5;
    int ntile = ga.M >> 4;

    for (int t = gw; t < ntile; t += nw) {
        int r0 = t * 16;
        const float* Ap = ga.A + (size_t)r0 * 32;
        uint32_t ahi[16], alo[16];
#pragma unroll
        for (int kc = 0; kc < 4; kc++) {
            float a0 = Ap[gid * 32 + kc * 8 + tig];
            float a1 = Ap[(gid + 8) * 32 + kc * 8 + tig];
            float a2 = Ap[gid * 32 + kc * 8 + tig + 4];
            float a3 = Ap[(gid + 8) * 32 + kc * 8 + tig + 4];
            uint32_t h;
            h = f2tf(a0); ahi[kc*4+0] = h; alo[kc*4+0] = f2tf(a0 - __uint_as_float(h));
            h = f2tf(a1); ahi[kc*4+1] = h; alo[kc*4+1] = f2tf(a1 - __uint_as_float(h));
            h = f2tf(a2); ahi[kc*4+2] = h; alo[kc*4+2] = f2tf(a2 - __uint_as_float(h));
            h = f2tf(a3); ahi[kc*4+3] = h; alo[kc*4+3] = f2tf(a3 - __uint_as_float(h));
        }
#pragma unroll
        for (int nt = 0; nt < NT; nt++) {
            const int m = nt >> 2;
            float d[4] = {0.f, 0.f, 0.f, 0.f};
#pragma unroll
            for (int kc = 0; kc < 4; kc++) {
                int i0 = (kc * 8 + tig) * PITCH + nt * 8 + gid;
                int i1 = i0 + 4 * PITCH;
                uint32_t bh0 = sB[0][i0], bh1 = sB[0][i1];
                uint32_t bl0 = sB[1][i0], bl1 = sB[1][i1];
                mma8(d, &ahi[kc * 4], bh0, bh1);
                mma8(d, &ahi[kc * 4], bl0, bl1);
                mma8(d, &alo[kc * 4], bh0, bh1);
            }
            int c = (nt & 3) * 8 + 2 * tig;
            float bv0 = ga.bias[m][c], bv1 = ga.bias[m][c + 1];
            int ra = r0 + gid, rb = r0 + gid + 8;
            float o0 = d[0] + bv0, o1 = d[1] + bv1;
            float o2 = d[2] + bv0, o3 = d[3] + bv1;
            if (MODE == 2) {
                o0 += g_aggr[ra * 32 + c]     + g_atom[ra * 32 + c];
                o1 += g_aggr[ra * 32 + c + 1] + g_atom[ra * 32 + c + 1];
                o2 += g_aggr[rb * 32 + c]     + g_atom[rb * 32 + c];
                o3 += g_aggr[rb * 32 + c + 1] + g_atom[rb * 32 + c + 1];
                o0 = fmaxf(o0, 0.f); o1 = fmaxf(o1, 0.f);
                o2 = fmaxf(o2, 0.f); o3 = fmaxf(o3, 0.f);
            }
            float* op = ga.out[m];
            *(float2*)&op[ra * 32 + c] = make_float2(o0, o1);
            *(float2*)&op[rb * 32 + c] = make_float2(o2, o3);
        }
    }
}

// ---- K0: atom_in = relu(x @ atom_w + atom_b); h = atom_in ----
__global__ void k_atom(const float* __restrict__ x,
                       const float* __restrict__ w,
                       const float* __restrict__ b) {
    int lane = threadIdx.x & 31;
    int gw = (blockIdx.x * blockDim.x + threadIdx.x) >> 5;
    int nw = (gridDim.x * blockDim.x) >> 5;
    float4 b4 = ((const float4*)b)[lane];
    for (int n = gw; n < NN; n += nw) {
        float4 xv = ((const float4*)x)[n * 32 + lane];
        float4 acc = b4;
#pragma unroll
        for (int k = 0; k < 128; k++) {
            float xk = __shfl_sync(FULL, ((const float*)&xv)[k & 3], k >> 2);
            float4 w4 = ((const float4*)w)[k * 32 + lane];
            acc.x += xk * w4.x; acc.y += xk * w4.y;
            acc.z += xk * w4.z; acc.w += xk * w4.w;
        }
        acc.x = fmaxf(acc.x, 0.f); acc.y = fmaxf(acc.y, 0.f);
        acc.z = fmaxf(acc.z, 0.f); acc.w = fmaxf(acc.w, 0.f);
        ((float4*)g_atom)[n * 32 + lane] = acc;
        ((float4*)g_h)[n * 32 + lane]   = acc;
    }
}

// ---- zero aggr/nsum, init nmax ----
__global__ void k_init() {
    int i = blockIdx.x * blockDim.x + threadIdx.x;
    int stride = gridDim.x * blockDim.x;
    for (int j = i; j < ROWS * F / 4; j += stride)
        ((float4*)g_aggr)[j] = make_float4(0.f, 0.f, 0.f, 0.f);
    for (int j = i; j < NN; j += stride) {
        g_nsum[j]  = 0.f;
        g_nmaxu[j] = 0x007FFFFFu;   // fenc(-inf)
    }
}

// ---- edge attention scores + segment max (warp/edge; lane = h*8+q) ----
__global__ void k_attn(const int* __restrict__ ei,
                       const float* __restrict__ dw, const float* __restrict__ db) {
    int lane = threadIdx.x & 31;
    int q = lane & 7;
    float4 dw4 = ((const float4*)dw)[q];
    float dbv = db[0];
    int gw = (blockIdx.x * blockDim.x + threadIdx.x) >> 5;
    int nw = (gridDim.x * blockDim.x) >> 5;
    for (int e = gw; e < NE; e += nw) {
        int s = __ldg(ei + e);
        int d = __ldg(ei + NE + e);
        float4 a = ((const float4*)g_xs)[d * 32 + lane];
        float4 c = ((const float4*)g_xd)[s * 32 + lane];
        float4 ea = ((const float4*)g_ea)[e * 8 + q];
        float v = fmaxf(a.x + c.x + ea.x, 0.f) * dw4.x;
        v += fmaxf(a.y + c.y + ea.y, 0.f) * dw4.y;
        v += fmaxf(a.z + c.z + ea.z, 0.f) * dw4.z;
        v += fmaxf(a.w + c.w + ea.w, 0.f) * dw4.w;
        v += __shfl_xor_sync(FULL, v, 4);
        v += __shfl_xor_sync(FULL, v, 2);
        v += __shfl_xor_sync(FULL, v, 1);
        v += dbv;
        float m = fmaxf(v, __shfl_xor_sync(FULL, v, 8));
        m = fmaxf(m, __shfl_xor_sync(FULL, m, 16));
        float ar = __shfl_sync(FULL, v, (lane & 3) * 8);
        if (lane < 4) g_exp[e * 4 + lane] = ar;
        if (lane == 0) atomicMax(&g_nmaxu[d], fenc(m));
    }
}

// ---- exp + segment sum ----
__global__ void k_exp(const int* __restrict__ ei) {
    int e = blockIdx.x * blockDim.x + threadIdx.x;
    if (e >= NE) return;
    int d = ei[NE + e];
    float nm = fdec(g_nmaxu[d]);
    float4 a = ((float4*)g_exp)[e];
    a.x = expf(a.x - nm); a.y = expf(a.y - nm);
    a.z = expf(a.z - nm); a.w = expf(a.w - nm);
    ((float4*)g_exp)[e] = a;
    atomicAdd(&g_nsum[d], a.x + a.y + a.z + a.w);
}

// ---- messages + tiled scatter (lane = j*8+q; one red.v4 per lane) ----
__global__ void k_msg(const int* __restrict__ ei) {
    int lane = threadIdx.x & 31;
    int q = lane & 7;
    int j = lane >> 3;
    int gw = (blockIdx.x * blockDim.x + threadIdx.x) >> 5;
    int nw = (gridDim.x * blockDim.x) >> 5;
    for (int g = gw; g < NG; g += nw) {
        float4 T = make_float4(0.f, 0.f, 0.f, 0.f);
#pragma unroll
        for (int c = 0; c < 4; c++) {
            int e = c * NG + g;
            int d = __ldg(ei + NE + e);
            float4 ex = ((const float4*)g_exp)[e];
            float inv = 1.f / (g_nsum[d] + 1e-8f);
            float exh = (j == 0) ? ex.x : (j == 1) ? ex.y : (j == 2) ? ex.z : ex.w;
            float sA = exh * inv;
            float4 xm = ((const float4*)g_xm)[d * 32 + lane];
            float4 em = ((const float4*)g_em)[e * 8 + q];
            T.x += sA * (xm.x + em.x);
            T.y += sA * (xm.y + em.y);
            T.z += sA * (xm.z + em.z);
            T.w += sA * (xm.w + em.w);
        }
        int tgt = __ldg(ei + NE + 4 * g + j);
        float* p = g_aggr + (size_t)tgt * 32 + q * 4;
        asm volatile("red.global.add.v4.f32 [%0], {%1,%2,%3,%4};"
                     :: "l"(p), "f"(T.x), "f"(T.y), "f"(T.z), "f"(T.w)
                     : "memory");
    }
}

// ---- out[n,f] = mean over heads ----
__global__ void k_mean(float* __restrict__ out) {
    int i = blockIdx.x * blockDim.x + threadIdx.x;
    if (i >= NN * F) return;
    int n = i >> 5;
    int f = i & 31;
    const float* p = g_h + n * 128 + f;
    out[i] = 0.25f * (p[0] + p[32] + p[64] + p[96]);
}

extern "C" void kernel_launch(void* const* d_in, const int* in_sizes, int n_in,
                              void* d_out, int out_size) {
    const float* x      = (const float*)d_in[0];
    const float* eattr  = (const float*)d_in[1];
    const int*   ei     = (const int*)d_in[2];
    const float* atom_w = (const float*)d_in[3];
    const float* atom_b = (const float*)d_in[4];
    const float* asw  = (const float*)d_in[5];
    const float* asb  = (const float*)d_in[6];
    const float* adw  = (const float*)d_in[7];
    const float* adb  = (const float*)d_in[8];
    const float* aew  = (const float*)d_in[9];
    const float* aeb  = (const float*)d_in[10];
    const float* dotw = (const float*)d_in[11];
    const float* dotb = (const float*)d_in[12];
    const float* mdw  = (const float*)d_in[13];
    const float* mdb  = (const float*)d_in[14];
    const float* mew  = (const float*)d_in[15];
    const float* meb  = (const float*)d_in[16];
    const float* wnw  = (const float*)d_in[17];
    const float* wnb  = (const float*)d_in[18];
    float* out = (float*)d_out;

    float* xs = nullptr; // device-global addresses resolved via symbols below

    k_atom<<<512, 256>>>(x, atom_w, atom_b);

    // resolve device-global pointers once (host-side address-of not allowed;
    // use kernels writing into fixed symbols instead -> pass via GArgs using
    // cudaGetSymbolAddress is host API (not alloc) but must not be in capture?
    // It IS capture-safe (pure host query), but simpler: kernels reference
    // globals directly; GArgs carries them via device-symbol addresses taken
    // below.
    (void)xs;
    static float *p_h = nullptr, *p_xs = nullptr, *p_xd = nullptr, *p_xm = nullptr,
                 *p_ea = nullptr, *p_em = nullptr;
    if (!p_h) {
        cudaGetSymbolAddress((void**)&p_h,  g_h);
        cudaGetSymbolAddress((void**)&p_xs, g_xs);
        cudaGetSymbolAddress((void**)&p_xd, g_xd);
        cudaGetSymbolAddress((void**)&p_xm, g_xm);
        cudaGetSymbolAddress((void**)&p_ea, g_ea);
        cudaGetSymbolAddress((void**)&p_em, g_em);
    }

    for (int l = 0; l < 2; l++) {
        int wo = l * 32 * 32, bo = l * 32;
        k_init<<<512, 256>>>();

        GArgs gn;
        gn.A = p_h; gn.M = ROWS;
        gn.B[0] = asw + wo; gn.B[1] = adw + wo; gn.B[2] = mdw + wo;
        gn.bias[0] = asb + bo; gn.bias[1] = adb + bo; gn.bias[2] = mdb + bo;
        gn.out[0] = p_xs; gn.out[1] = p_xd; gn.out[2] = p_xm;
        k_gemm<3, 0><<<512, 256>>>(gn);

        GArgs ge;
        ge.A = eattr; ge.M = NE;
        ge.B[0] = aew + wo; ge.B[1] = mew + wo; ge.B[2] = aew + wo;
        ge.bias[0] = aeb + bo; ge.bias[1] = meb + bo; ge.bias[2] = aeb + bo;
        ge.out[0] = p_ea; ge.out[1] = p_em; ge.out[2] = p_ea;
        k_gemm<2, 0><<<640, 256>>>(ge);

        k_attn<<<1024, 256>>>(ei, dotw + l * 32, dotb + l);
        k_exp<<<(NE + 255) / 256, 256>>>(ei);
        k_msg<<<1024, 256>>>(ei);

        GArgs gc;
        gc.A = p_h; gc.M = ROWS;
        gc.B[0] = wnw + wo; gc.B[1] = wnw + wo; gc.B[2] = wnw + wo;
        gc.bias[0] = wnb + bo; gc.bias[1] = wnb + bo; gc.bias[2] = wnb + bo;
        gc.out[0] = p_h; gc.out[1] = p_h; gc.out[2] = p_h;
        k_gemm<1, 2><<<512, 256>>>(gc);
    }
    k_mean<<<(NN * F + 255) / 256, 256>>>(out);
}

// round 4
// speedup vs baseline: 1.6369x; 1.2461x over previous
#include <cuda_runtime.h>
#include <cstdint>

#define FULL 0xffffffffu

constexpr int NN   = 50000;
constexpr int NE   = 400000;
constexpr int F    = 32;
constexpr int H    = 4;
constexpr int ROWS = NN * H;        // 200000 (n,h) rows
constexpr int NG   = NE / H;        // 100000 message groups

// ---- scratch (device globals; no allocation allowed) ----
__device__ float    g_h[ROWS * F];
__device__ float    g_atom[ROWS * F];
__device__ float    g_xs[ROWS * F];
__device__ float    g_xd[ROWS * F];
__device__ float    g_xm[ROWS * F];
__device__ float    g_ea[NE * F];
__device__ float    g_em[NE * F];
__device__ float    g_exp[NE * H];
__device__ unsigned g_nmaxu[NN];
__device__ float    g_nsum[NN];
__device__ float    g_aggr[ROWS * F];

__device__ __forceinline__ unsigned fenc(float f) {
    unsigned u = __float_as_uint(f);
    return (u & 0x80000000u) ? ~u : (u | 0x80000000u);
}
__device__ __forceinline__ float fdec(unsigned u) {
    return __uint_as_float((u & 0x80000000u) ? (u & 0x7fffffffu) : ~u);
}

__device__ __forceinline__ uint32_t f2tf(float v) {
    uint32_t r;
    asm("cvt.rna.tf32.f32 %0, %1;" : "=r"(r) : "f"(v));
    return r;
}

__device__ __forceinline__ void mma8(float d[4], const uint32_t a[4],
                                     uint32_t b0, uint32_t b1) {
    asm("mma.sync.aligned.m16n8k8.row.col.f32.tf32.tf32.f32 "
        "{%0,%1,%2,%3}, {%4,%5,%6,%7}, {%8,%9}, {%0,%1,%2,%3};"
        : "+f"(d[0]), "+f"(d[1]), "+f"(d[2]), "+f"(d[3])
        : "r"(a[0]), "r"(a[1]), "r"(a[2]), "r"(a[3]), "r"(b0), "r"(b1));
}

struct GArgs {
    const float* A;
    const float* B[4];
    const float* bias[4];
    float*       out[4];
    float*       out2[4];   // MODE 1 dual-write
    int          M;
    int          Astride;
    int          Bstride;
    int          Ostride;
};

// ---- generic GEMM: out[m] = A @ B[m] + bias[m], K = KC*8, N = 32 per matrix
// 3xTF32 split for ~fp32 accuracy. MODE 0 plain; MODE 1 relu + dual write;
// MODE 2 comb epilogue (+g_aggr +g_atom, relu).
// Streaming k-chunks with A prefetch to keep registers low.
template<int NM, int KC, int MODE>
__global__ void __launch_bounds__(256) k_gemm(GArgs ga) {
    constexpr int NT = NM * 4;           // 8-col n-tiles
    constexpr int PITCH = NM * 32 + 8;   // PITCH % 32 == 8 -> conflict-free
    constexpr int K = KC * 8;
    extern __shared__ uint32_t sB[];
    uint32_t* sB0 = sB;
    uint32_t* sB1 = sB + K * PITCH;

    int tid = threadIdx.x;
    // stage B hi/lo (tf32 split), float4 loads
    for (int m = 0; m < NM; m++) {
        const float* Bp = ga.B[m];
        for (int i = tid; i < K * 8; i += 256) {
            int k = i >> 3, nq = i & 7;
            float4 v = *(const float4*)(Bp + (size_t)k * ga.Bstride + nq * 4);
            int base = k * PITCH + m * 32 + nq * 4;
            uint32_t hx;
            hx = f2tf(v.x); sB0[base+0] = hx; sB1[base+0] = f2tf(v.x - __uint_as_float(hx));
            hx = f2tf(v.y); sB0[base+1] = hx; sB1[base+1] = f2tf(v.y - __uint_as_float(hx));
            hx = f2tf(v.z); sB0[base+2] = hx; sB1[base+2] = f2tf(v.z - __uint_as_float(hx));
            hx = f2tf(v.w); sB0[base+3] = hx; sB1[base+3] = f2tf(v.w - __uint_as_float(hx));
        }
    }
    __syncthreads();

    int lane = tid & 31;
    int gid = lane >> 2, tig = lane & 3;
    int gw = (blockIdx.x * 256 + tid) >> 5;
    int nw = (gridDim.x * 256) >> 5;
    int ntile = ga.M >> 4;
    const int As = ga.Astride;

    for (int t = gw; t < ntile; t += nw) {
        const float* Ap = ga.A + (size_t)(t * 16) * As;
        float d[NT][4];
#pragma unroll
        for (int nt = 0; nt < NT; nt++) {
            d[nt][0] = 0.f; d[nt][1] = 0.f; d[nt][2] = 0.f; d[nt][3] = 0.f;
        }
        float a0 = Ap[gid * As + tig];
        float a1 = Ap[(gid + 8) * As + tig];
        float a2 = Ap[gid * As + tig + 4];
        float a3 = Ap[(gid + 8) * As + tig + 4];
#pragma unroll 1
        for (int kc = 0; kc < KC; kc++) {
            float n0 = 0.f, n1 = 0.f, n2 = 0.f, n3 = 0.f;
            if (kc + 1 < KC) {
                int c0 = (kc + 1) * 8 + tig;
                n0 = Ap[gid * As + c0];
                n1 = Ap[(gid + 8) * As + c0];
                n2 = Ap[gid * As + c0 + 4];
                n3 = Ap[(gid + 8) * As + c0 + 4];
            }
            uint32_t ah[4], al[4];
            ah[0] = f2tf(a0); al[0] = f2tf(a0 - __uint_as_float(ah[0]));
            ah[1] = f2tf(a1); al[1] = f2tf(a1 - __uint_as_float(ah[1]));
            ah[2] = f2tf(a2); al[2] = f2tf(a2 - __uint_as_float(ah[2]));
            ah[3] = f2tf(a3); al[3] = f2tf(a3 - __uint_as_float(ah[3]));
            int krow = (kc * 8 + tig) * PITCH + gid;
#pragma unroll
            for (int nt = 0; nt < NT; nt++) {
                int i0 = krow + nt * 8;
                uint32_t bh0 = sB0[i0], bh1 = sB0[i0 + 4 * PITCH];
                uint32_t bl0 = sB1[i0], bl1 = sB1[i0 + 4 * PITCH];
                mma8(d[nt], ah, bh0, bh1);
                mma8(d[nt], ah, bl0, bl1);
                mma8(d[nt], al, bh0, bh1);
            }
            a0 = n0; a1 = n1; a2 = n2; a3 = n3;
        }
        int ra = t * 16 + gid, rb = ra + 8;
#pragma unroll
        for (int nt = 0; nt < NT; nt++) {
            const int m = nt >> 2;
            int c = (nt & 3) * 8 + 2 * tig;
            float bv0 = ga.bias[m][c], bv1 = ga.bias[m][c + 1];
            float o0 = d[nt][0] + bv0, o1 = d[nt][1] + bv1;
            float o2 = d[nt][2] + bv0, o3 = d[nt][3] + bv1;
            if (MODE == 2) {
                int ia = ra * 32 + c, ib = rb * 32 + c;
                o0 += g_aggr[ia]     + g_atom[ia];
                o1 += g_aggr[ia + 1] + g_atom[ia + 1];
                o2 += g_aggr[ib]     + g_atom[ib];
                o3 += g_aggr[ib + 1] + g_atom[ib + 1];
            }
            if (MODE != 0) {
                o0 = fmaxf(o0, 0.f); o1 = fmaxf(o1, 0.f);
                o2 = fmaxf(o2, 0.f); o3 = fmaxf(o3, 0.f);
            }
            float* op = ga.out[m];
            *(float2*)&op[(size_t)ra * ga.Ostride + c] = make_float2(o0, o1);
            *(float2*)&op[(size_t)rb * ga.Ostride + c] = make_float2(o2, o3);
            if (MODE == 1) {
                float* op2 = ga.out2[m];
                *(float2*)&op2[(size_t)ra * ga.Ostride + c] = make_float2(o0, o1);
                *(float2*)&op2[(size_t)rb * ga.Ostride + c] = make_float2(o2, o3);
            }
        }
    }
}

// ---- zero aggr/nsum, init nmax ----
__global__ void k_init() {
    int i = blockIdx.x * blockDim.x + threadIdx.x;
    int stride = gridDim.x * blockDim.x;
    for (int j = i; j < ROWS * F / 4; j += stride)
        ((float4*)g_aggr)[j] = make_float4(0.f, 0.f, 0.f, 0.f);
    for (int j = i; j < NN; j += stride) {
        g_nsum[j]  = 0.f;
        g_nmaxu[j] = 0x007FFFFFu;   // fenc(-inf)
    }
}

// ---- edge attention scores + segment max (warp/edge; lane = h*8+q) ----
__global__ void k_attn(const int* __restrict__ ei,
                       const float* __restrict__ dw, const float* __restrict__ db) {
    int lane = threadIdx.x & 31;
    int q = lane & 7;
    float4 dw4 = ((const float4*)dw)[q];
    float dbv = db[0];
    int gw = (blockIdx.x * blockDim.x + threadIdx.x) >> 5;
    int nw = (gridDim.x * blockDim.x) >> 5;
    for (int e = gw; e < NE; e += nw) {
        int s = __ldg(ei + e);
        int d = __ldg(ei + NE + e);
        float4 a = ((const float4*)g_xs)[d * 32 + lane];
        float4 c = ((const float4*)g_xd)[s * 32 + lane];
        float4 ea = ((const float4*)g_ea)[e * 8 + q];
        float v = fmaxf(a.x + c.x + ea.x, 0.f) * dw4.x;
        v += fmaxf(a.y + c.y + ea.y, 0.f) * dw4.y;
        v += fmaxf(a.z + c.z + ea.z, 0.f) * dw4.z;
        v += fmaxf(a.w + c.w + ea.w, 0.f) * dw4.w;
        v += __shfl_xor_sync(FULL, v, 4);
        v += __shfl_xor_sync(FULL, v, 2);
        v += __shfl_xor_sync(FULL, v, 1);
        v += dbv;
        float m = fmaxf(v, __shfl_xor_sync(FULL, v, 8));
        m = fmaxf(m, __shfl_xor_sync(FULL, m, 16));
        float ar = __shfl_sync(FULL, v, (lane & 3) * 8);
        if (lane < 4) g_exp[e * 4 + lane] = ar;
        if (lane == 0) atomicMax(&g_nmaxu[d], fenc(m));
    }
}

// ---- exp + segment sum ----
__global__ void k_exp(const int* __restrict__ ei) {
    int e = blockIdx.x * blockDim.x + threadIdx.x;
    if (e >= NE) return;
    int d = ei[NE + e];
    float nm = fdec(g_nmaxu[d]);
    float4 a = ((float4*)g_exp)[e];
    a.x = expf(a.x - nm); a.y = expf(a.y - nm);
    a.z = expf(a.z - nm); a.w = expf(a.w - nm);
    ((float4*)g_exp)[e] = a;
    atomicAdd(&g_nsum[d], a.x + a.y + a.z + a.w);
}

// ---- messages + tiled scatter (lane = j*8+q; one red.v4 per lane) ----
__global__ void k_msg(const int* __restrict__ ei) {
    int lane = threadIdx.x & 31;
    int q = lane & 7;
    int j = lane >> 3;
    int gw = (blockIdx.x * blockDim.x + threadIdx.x) >> 5;
    int nw = (gridDim.x * blockDim.x) >> 5;
    for (int g = gw; g < NG; g += nw) {
        float4 T = make_float4(0.f, 0.f, 0.f, 0.f);
#pragma unroll
        for (int c = 0; c < 4; c++) {
            int e = c * NG + g;
            int d = __ldg(ei + NE + e);
            float4 ex = ((const float4*)g_exp)[e];
            float inv = 1.f / (g_nsum[d] + 1e-8f);
            float exh = (j == 0) ? ex.x : (j == 1) ? ex.y : (j == 2) ? ex.z : ex.w;
            float sA = exh * inv;
            float4 xm = ((const float4*)g_xm)[d * 32 + lane];
            float4 em = ((const float4*)g_em)[e * 8 + q];
            T.x += sA * (xm.x + em.x);
            T.y += sA * (xm.y + em.y);
            T.z += sA * (xm.z + em.z);
            T.w += sA * (xm.w + em.w);
        }
        int tgt = __ldg(ei + NE + 4 * g + j);
        float* p = g_aggr + (size_t)tgt * 32 + q * 4;
        asm volatile("red.global.add.v4.f32 [%0], {%1,%2,%3,%4};"
                     :: "l"(p), "f"(T.x), "f"(T.y), "f"(T.z), "f"(T.w)
                     : "memory");
    }
}

// ---- out[n,f] = mean over heads ----
__global__ void k_mean(float* __restrict__ out) {
    int i = blockIdx.x * blockDim.x + threadIdx.x;
    if (i >= NN * F) return;
    int n = i >> 5;
    int f = i & 31;
    const float* p = g_h + n * 128 + f;
    out[i] = 0.25f * (p[0] + p[32] + p[64] + p[96]);
}

extern "C" void kernel_launch(void* const* d_in, const int* in_sizes, int n_in,
                              void* d_out, int out_size) {
    const float* x      = (const float*)d_in[0];
    const float* eattr  = (const float*)d_in[1];
    const int*   ei     = (const int*)d_in[2];
    const float* atom_w = (const float*)d_in[3];
    const float* atom_b = (const float*)d_in[4];
    const float* asw  = (const float*)d_in[5];
    const float* asb  = (const float*)d_in[6];
    const float* adw  = (const float*)d_in[7];
    const float* adb  = (const float*)d_in[8];
    const float* aew  = (const float*)d_in[9];
    const float* aeb  = (const float*)d_in[10];
    const float* dotw = (const float*)d_in[11];
    const float* dotb = (const float*)d_in[12];
    const float* mdw  = (const float*)d_in[13];
    const float* mdb  = (const float*)d_in[14];
    const float* mew  = (const float*)d_in[15];
    const float* meb  = (const float*)d_in[16];
    const float* wnw  = (const float*)d_in[17];
    const float* wnb  = (const float*)d_in[18];
    float* out = (float*)d_out;

    float *p_h, *p_atom, *p_xs, *p_xd, *p_xm, *p_ea, *p_em;
    cudaGetSymbolAddress((void**)&p_h,    g_h);
    cudaGetSymbolAddress((void**)&p_atom, g_atom);
    cudaGetSymbolAddress((void**)&p_xs,   g_xs);
    cudaGetSymbolAddress((void**)&p_xd,   g_xd);
    cudaGetSymbolAddress((void**)&p_xm,   g_xm);
    cudaGetSymbolAddress((void**)&p_ea,   g_ea);
    cudaGetSymbolAddress((void**)&p_em,   g_em);

    // dynamic smem sizes: 2 * K * PITCH * 4 bytes
    const int smem_atom = 2 * 128 * (4 * 32 + 8) * 4;   // 139264
    const int smem_n3   = 2 * 32 * (3 * 32 + 8) * 4;    // 26624
    const int smem_e2   = 2 * 32 * (2 * 32 + 8) * 4;    // 18432
    const int smem_c1   = 2 * 32 * (1 * 32 + 8) * 4;    // 10240
    cudaFuncSetAttribute(k_gemm<4, 16, 1>,
                         cudaFuncAttributeMaxDynamicSharedMemorySize, smem_atom);

    // atom: (50000 x 128) @ (128 x 128), relu, dual write to g_atom / g_h
    {
        GArgs ga;
        ga.A = x; ga.M = NN; ga.Astride = 128; ga.Bstride = 128; ga.Ostride = 128;
        for (int m = 0; m < 4; m++) {
            ga.B[m]    = atom_w + m * 32;
            ga.bias[m] = atom_b + m * 32;
            ga.out[m]  = p_atom + m * 32;
            ga.out2[m] = p_h    + m * 32;
        }
        k_gemm<4, 16, 1><<<148, 256, smem_atom>>>(ga);
    }

    for (int l = 0; l < 2; l++) {
        int wo = l * 32 * 32, bo = l * 32;
        k_init<<<512, 256>>>();

        GArgs gn;
        gn.A = p_h; gn.M = ROWS; gn.Astride = 32; gn.Bstride = 32; gn.Ostride = 32;
        gn.B[0] = asw + wo; gn.B[1] = adw + wo; gn.B[2] = mdw + wo; gn.B[3] = asw + wo;
        gn.bias[0] = asb + bo; gn.bias[1] = adb + bo; gn.bias[2] = mdb + bo; gn.bias[3] = asb + bo;
        gn.out[0] = p_xs; gn.out[1] = p_xd; gn.out[2] = p_xm; gn.out[3] = p_xs;
        gn.out2[0] = gn.out2[1] = gn.out2[2] = gn.out2[3] = p_xs;
        k_gemm<3, 4, 0><<<444, 256, smem_n3>>>(gn);

        GArgs ge;
        ge.A = eattr; ge.M = NE; ge.Astride = 32; ge.Bstride = 32; ge.Ostride = 32;
        ge.B[0] = aew + wo; ge.B[1] = mew + wo; ge.B[2] = aew + wo; ge.B[3] = aew + wo;
        ge.bias[0] = aeb + bo; ge.bias[1] = meb + bo; ge.bias[2] = aeb + bo; ge.bias[3] = aeb + bo;
        ge.out[0] = p_ea; ge.out[1] = p_em; ge.out[2] = p_ea; ge.out[3] = p_ea;
        ge.out2[0] = ge.out2[1] = ge.out2[2] = ge.out2[3] = p_ea;
        k_gemm<2, 4, 0><<<444, 256, smem_e2>>>(ge);

        k_attn<<<1024, 256>>>(ei, dotw + l * 32, dotb + l);
        k_exp<<<(NE + 255) / 256, 256>>>(ei);
        k_msg<<<1024, 256>>>(ei);

        GArgs gc;
        gc.A = p_h; gc.M = ROWS; gc.Astride = 32; gc.Bstride = 32; gc.Ostride = 32;
        gc.B[0] = wnw + wo; gc.B[1] = wnw + wo; gc.B[2] = wnw + wo; gc.B[3] = wnw + wo;
        gc.bias[0] = wnb + bo; gc.bias[1] = wnb + bo; gc.bias[2] = wnb + bo; gc.bias[3] = wnb + bo;
        gc.out[0] = p_h; gc.out[1] = p_h; gc.out[2] = p_h; gc.out[3] = p_h;
        gc.out2[0] = gc.out2[1] = gc.out2[2] = gc.out2[3] = p_h;
        k_gemm<1, 4, 2><<<444, 256, smem_c1>>>(gc);
    }
    k_mean<<<(NN * F + 255) / 256, 256>>>(out);
}